// round 12
// baseline (speedup 1.0000x reference)
#include <cuda_runtime.h>

// CRF NLL: B=1024, T=512, K=64, START=62, STOP=63
// Exp-domain forward recursion. Persistent warps (148 CTAs x 4 = 592, one per
// SMSP), LPT order via atomic counter. v in registers (2 elems/lane),
// broadcast via PIPELINED __shfl_sync: 8-pair chunks double-buffered so the
// shfl batch for chunk c+1 issues while chunk c feeds 4 fma2 accumulator
// chains. Et = exp(trans) register-resident once per warp.

#define B_ 1024
#define T_ 512
#define K_ 64
#define START_ 62
#define STOP_ 63

typedef unsigned long long u64;

__device__ int g_order[B_];
__device__ int g_counter;

__device__ __forceinline__ u64 fma2(u64 a, u64 b, u64 c) {
    u64 d;
    asm("fma.rn.f32x2 %0, %1, %2, %3;" : "=l"(d) : "l"(a), "l"(b), "l"(c));
    return d;
}
__device__ __forceinline__ u64 add2(u64 a, u64 b) {
    u64 d;
    asm("add.rn.f32x2 %0, %1, %2;" : "=l"(d) : "l"(a), "l"(b));
    return d;
}
__device__ __forceinline__ u64 pack2(float lo, float hi) {
    u64 d;
    asm("mov.b64 %0, {%1, %2};" : "=l"(d) : "f"(lo), "f"(hi));
    return d;
}
__device__ __forceinline__ float sum2(u64 a) {
    float lo, hi;
    asm("mov.b64 {%0, %1}, %2;" : "=f"(lo), "=f"(hi) : "l"(a));
    return lo + hi;
}
__device__ __forceinline__ float pmax2(u64 a) {   // max of 2 packed floats (>=0)
    float lo, hi;
    asm("mov.b64 {%0, %1}, %2;" : "=f"(lo), "=f"(hi) : "l"(a));
    return fmaxf(lo, hi);
}

// Rank batches by descending length; zero accumulator + work counter.
__global__ void order_kernel(const int* __restrict__ lengths, float* out) {
    __shared__ int L[B_];
    const int tid = threadIdx.x;                 // 256 threads, grid 4
    for (int j = tid; j < B_; j += 256) L[j] = lengths[j];
    __syncthreads();
    const int b = blockIdx.x * 256 + tid;
    const int mylen = L[b];
    int rank = 0;
    for (int j = 0; j < B_; ++j) {
        int lj = L[j];
        rank += (lj > mylen) || (lj == mylen && j < b);
    }
    g_order[rank] = b;
    if (b == 0) { out[0] = 0.0f; g_counter = 0; }
}

__global__ void __launch_bounds__(128, 1) crf_shfl(
    const float* __restrict__ feats,      // [B,T,K]
    const int*   __restrict__ lengths,    // [B]
    const int*   __restrict__ tags,       // [B,T]
    const float* __restrict__ trans,      // [K,K] trans[next, prev]
    float* __restrict__ out)
{
    const int lane = threadIdx.x & 31;    // owns rows/elems 2*lane, 2*lane+1

    // ---- Et rows 2*lane, 2*lane+1, packed over column pairs; ONCE per warp --
    u64 EtA2[32], EtB2[32];
#pragma unroll
    for (int q = 0; q < 32; ++q) {
        EtA2[q] = pack2(__expf(trans[(2 * lane)     * K_ + 2 * q]),
                        __expf(trans[(2 * lane)     * K_ + 2 * q + 1]));
        EtB2[q] = pack2(__expf(trans[(2 * lane + 1) * K_ + 2 * q]),
                        __expf(trans[(2 * lane + 1) * K_ + 2 * q + 1]));
    }
    const float EtS0 = __expf(trans[STOP_ * K_ + 2 * lane]);
    const float EtS1 = __expf(trans[STOP_ * K_ + 2 * lane + 1]);

    for (;;) {
        // ---- grab next batch (longest remaining first) ----
        int r = 0;
        if (lane == 0) r = atomicAdd(&g_counter, 1);
        r = __shfl_sync(0xFFFFFFFFu, r, 0);
        if (r >= B_) break;
        const int b   = g_order[r];
        const int len = lengths[b];

        const float*  fb  = feats + (size_t)b * (T_ * K_);
        const float2* fb2 = (const float2*)fb;          // [T][32]
        const int*    tb  = tags + (size_t)b * T_;

        // ---- gold score, parallel over t ----
        float gold = 0.0f;
#pragma unroll
        for (int q = 0; q < 16; ++q) {
            int t = lane + 32 * q;
            if (t < len) {
                int tg = tb[t];
                int pv = t ? tb[t - 1] : START_;
                gold += fb[t * K_ + tg] + trans[tg * K_ + pv];
            }
        }
        if (lane == 0) gold += trans[STOP_ * K_ + tb[len - 1]];

        // ---- v0 in registers: 1 at START, 0 elsewhere ----
        float w0 = (2 * lane     == START_) ? 1.0f : 0.0f;
        float w1 = (2 * lane + 1 == START_) ? 1.0f : 0.0f;

        // ---- emission group 0..3, exp'd ----
        float2 c0 = fb2[0 * 32 + lane], c1 = fb2[1 * 32 + lane],
               c2 = fb2[2 * 32 + lane], c3 = fb2[3 * 32 + lane];
        float2 ce0 = make_float2(__expf(c0.x), __expf(c0.y));
        float2 ce1 = make_float2(__expf(c1.x), __expf(c1.y));
        float2 ce2 = make_float2(__expf(c2.x), __expf(c2.y));
        float2 ce3 = make_float2(__expf(c3.x), __expf(c3.y));

        int ktot = 0;
        const int len4 = len & ~3;

        // One step: pipelined broadcast. x/y are 8-pair (16-value) chunks.
        // All shfls of a chunk are batched before their fma block, and the
        // following chunk's shfls are batched before the current fma block
        // retires, so shfl latency (26) and the 4 fma2 chains overlap.
#define SHFL_CHUNK(DST, BASE)                                              \
        _Pragma("unroll")                                                  \
        for (int j = 0; j < 8; ++j)                                        \
            DST[j] = pack2(__shfl_sync(0xFFFFFFFFu, w0, (BASE) + j),       \
                           __shfl_sync(0xFFFFFFFFu, w1, (BASE) + j));

#define FMA_CHUNK(SRC, BASE)                                               \
        _Pragma("unroll")                                                  \
        for (int j = 0; j < 8; j += 2) {                                   \
            a0 = fma2(EtA2[(BASE) + j],     SRC[j],     a0);               \
            b0 = fma2(EtB2[(BASE) + j],     SRC[j],     b0);               \
            a1 = fma2(EtA2[(BASE) + j + 1], SRC[j + 1], a1);               \
            b1 = fma2(EtB2[(BASE) + j + 1], SRC[j + 1], b1);               \
        }

#define STEP(CE, RESC)                                                     \
    {                                                                      \
        u64 x[8], y[8];                                                    \
        u64 a0 = 0ull, a1 = 0ull, b0 = 0ull, b1 = 0ull;                    \
        SHFL_CHUNK(x, 0)                                                   \
        SHFL_CHUNK(y, 8)                                                   \
        FMA_CHUNK(x, 0)                                                    \
        SHFL_CHUNK(x, 16)                                                  \
        FMA_CHUNK(y, 8)                                                    \
        SHFL_CHUNK(y, 24)                                                  \
        float mx = 0.0f;                                                   \
        if (RESC) {                                                        \
            _Pragma("unroll")                                              \
            for (int j = 0; j < 8; ++j)                                    \
                mx = fmaxf(mx, fmaxf(pmax2(x[j]), pmax2(y[j])));           \
        }                                                                  \
        FMA_CHUNK(x, 16)                                                   \
        FMA_CHUNK(y, 24)                                                   \
        float nw0 = sum2(add2(a0, a1)) * (CE).x;                           \
        float nw1 = sum2(add2(b0, b1)) * (CE).y;                           \
        if (RESC) {                                                        \
            /* mx from chunks 0,1 only: it is a power-of-2 UNDER-estimate  \
               is not acceptable -- so fold chunks 2,3 in too */           \
            _Pragma("unroll")                                              \
            for (int j = 0; j < 8; ++j)                                    \
                mx = fmaxf(mx, fmaxf(pmax2(x[j]), pmax2(y[j])));           \
            /* mx identical on all lanes (built from broadcast values) */  \
            if (mx > 0.0f) {                                               \
                int k = ((__float_as_int(mx) >> 23) & 0xFF) - 127;         \
                ktot += k;                                                 \
                float sc = __int_as_float((127 - k) << 23);                \
                nw0 *= sc; nw1 *= sc;                                      \
            }                                                              \
        }                                                                  \
        w0 = nw0; w1 = nw1;                                                \
    }

        for (int t0 = 0; t0 < len4; t0 += 4) {
            // load next group's raw emissions (clamped; garbage never used)
            const int p = min(t0 + 4, T_ - 4);
            float2 g0 = fb2[(p + 0) * 32 + lane];
            float2 g1 = fb2[(p + 1) * 32 + lane];
            float2 g2 = fb2[(p + 2) * 32 + lane];
            float2 g3 = fb2[(p + 3) * 32 + lane];

            STEP(ce0, false);
            STEP(ce1, false);
            STEP(ce2, false);
            STEP(ce3, true);

            ce0 = make_float2(__expf(g0.x), __expf(g0.y));
            ce1 = make_float2(__expf(g1.x), __expf(g1.y));
            ce2 = make_float2(__expf(g2.x), __expf(g2.y));
            ce3 = make_float2(__expf(g3.x), __expf(g3.y));
        }

        // remainder (0-3 steps; <=3 unscaled steps cannot overflow)
        const int rem = len - len4;
        if (rem > 0) STEP(ce0, false);
        if (rem > 1) STEP(ce1, false);
        if (rem > 2) STEP(ce2, false);
#undef STEP
#undef SHFL_CHUNK
#undef FMA_CHUNK

        // ---- terminal: fwd = ktot*ln2 + log(sum_i v[i]*exp(trans[STOP,i])) --
        float u = w0 * EtS0 + w1 * EtS1;
#pragma unroll
        for (int off = 16; off; off >>= 1) {
            u    += __shfl_xor_sync(0xFFFFFFFFu, u,    off);
            gold += __shfl_xor_sync(0xFFFFFFFFu, gold, off);
        }
        if (lane == 0) {
            float fwd = (float)((double)ktot * 0.69314718055994530942)
                      + logf(u);
            atomicAdd(out, (fwd - gold) * (1.0f / (float)B_));
        }
    }
}

extern "C" void kernel_launch(void* const* d_in, const int* in_sizes, int n_in,
                              void* d_out, int out_size)
{
    const float* feats   = (const float*)d_in[0];
    const int*   lengths = (const int*)  d_in[1];
    const int*   tags    = (const int*)  d_in[2];
    const float* trans   = (const float*)d_in[3];
    float* out = (float*)d_out;

    order_kernel<<<4, 256>>>(lengths, out);
    crf_shfl<<<148, 128>>>(feats, lengths, tags, trans, out);
}

// round 14
// speedup vs baseline: 1.3297x; 1.3297x over previous
#include <cuda_runtime.h>
#include <cuda_bf16.h>

// CRF NLL: B=1024, T=512, K=64, START=62, STOP=63
// Exp-domain forward recursion in BF16: persistent warps (148 CTAs x 4 = 592,
// one per SMSP), LPT order via atomic counter. v[64] packed as 32 bf16x2
// (one per lane), broadcast = 32 SHFLs; matvec = 64 HFMA2 (rt=2, no RF-bank
// penalty). Emission exp + final scaling stay fp32. Et = bf16(exp(trans)),
// register-resident once per warp.

#define B_ 1024
#define T_ 512
#define K_ 64
#define START_ 62
#define STOP_ 63

typedef unsigned int u32;

__device__ int g_order[B_];
__device__ int g_counter;

__device__ __forceinline__ __nv_bfloat162 as_bf2(u32 x) {
    return *reinterpret_cast<__nv_bfloat162*>(&x);
}
__device__ __forceinline__ u32 as_u32(__nv_bfloat162 x) {
    return *reinterpret_cast<u32*>(&x);
}

// Rank batches by descending length; zero accumulator + work counter.
__global__ void order_kernel(const int* __restrict__ lengths, float* out) {
    __shared__ int L[B_];
    const int tid = threadIdx.x;                 // 256 threads, grid 4
    for (int j = tid; j < B_; j += 256) L[j] = lengths[j];
    __syncthreads();
    const int b = blockIdx.x * 256 + tid;
    const int mylen = L[b];
    int rank = 0;
    for (int j = 0; j < B_; ++j) {
        int lj = L[j];
        rank += (lj > mylen) || (lj == mylen && j < b);
    }
    g_order[rank] = b;
    if (b == 0) { out[0] = 0.0f; g_counter = 0; }
}

__global__ void __launch_bounds__(128, 1) crf_bf16(
    const float* __restrict__ feats,      // [B,T,K]
    const int*   __restrict__ lengths,    // [B]
    const int*   __restrict__ tags,       // [B,T]
    const float* __restrict__ trans,      // [K,K] trans[next, prev]
    float* __restrict__ out)
{
    const int lane = threadIdx.x & 31;    // owns rows/elems 2*lane, 2*lane+1

    // ---- Et rows 2*lane, 2*lane+1 as bf16x2 over column pairs; once/warp ----
    __nv_bfloat162 EtA[32], EtB[32];
#pragma unroll
    for (int q = 0; q < 32; ++q) {
        EtA[q] = __floats2bfloat162_rn(__expf(trans[(2 * lane)     * K_ + 2 * q]),
                                       __expf(trans[(2 * lane)     * K_ + 2 * q + 1]));
        EtB[q] = __floats2bfloat162_rn(__expf(trans[(2 * lane + 1) * K_ + 2 * q]),
                                       __expf(trans[(2 * lane + 1) * K_ + 2 * q + 1]));
    }
    const float EtS0 = __expf(trans[STOP_ * K_ + 2 * lane]);
    const float EtS1 = __expf(trans[STOP_ * K_ + 2 * lane + 1]);

    for (;;) {
        // ---- grab next batch (longest remaining first) ----
        int r = 0;
        if (lane == 0) r = atomicAdd(&g_counter, 1);
        r = __shfl_sync(0xFFFFFFFFu, r, 0);
        if (r >= B_) break;
        const int b   = g_order[r];
        const int len = lengths[b];

        const float*  fb  = feats + (size_t)b * (T_ * K_);
        const float2* fb2 = (const float2*)fb;          // [T][32]
        const int*    tb  = tags + (size_t)b * T_;

        // ---- gold score, parallel over t (fp32, exact) ----
        float gold = 0.0f;
#pragma unroll
        for (int q = 0; q < 16; ++q) {
            int t = lane + 32 * q;
            if (t < len) {
                int tg = tb[t];
                int pv = t ? tb[t - 1] : START_;
                gold += fb[t * K_ + tg] + trans[tg * K_ + pv];
            }
        }
        if (lane == 0) gold += trans[STOP_ * K_ + tb[len - 1]];

        // ---- v0 packed: 1 at START, 0 elsewhere ----
        u32 wpack = as_u32(__floats2bfloat162_rn(
            (2 * lane     == START_) ? 1.0f : 0.0f,
            (2 * lane + 1 == START_) ? 1.0f : 0.0f));

        // ---- emission group 0..3, exp'd in fp32 ----
        float2 c0 = fb2[0 * 32 + lane], c1 = fb2[1 * 32 + lane],
               c2 = fb2[2 * 32 + lane], c3 = fb2[3 * 32 + lane];
        float2 ce0 = make_float2(__expf(c0.x), __expf(c0.y));
        float2 ce1 = make_float2(__expf(c1.x), __expf(c1.y));
        float2 ce2 = make_float2(__expf(c2.x), __expf(c2.y));
        float2 ce3 = make_float2(__expf(c3.x), __expf(c3.y));

        int ktot = 0;
        const int len4 = len & ~3;

        // One step: 32 SHFL broadcast of bf16x2 pairs, 64 HFMA2 (4 chains),
        // fp32 epilogue (horizontal sum, *exp(emit), optional 2^-k rescale).
#define STEP(CE, RESC)                                                     \
    {                                                                      \
        u32 xb[32];                                                        \
        _Pragma("unroll")                                                  \
        for (int j = 0; j < 16; ++j)                                       \
            xb[j] = __shfl_sync(0xFFFFFFFFu, wpack, j);                    \
        __nv_bfloat162 z = __floats2bfloat162_rn(0.f, 0.f);                \
        __nv_bfloat162 aA0 = z, aA1 = z, aB0 = z, aB1 = z;                 \
        _Pragma("unroll")                                                  \
        for (int j = 16; j < 32; ++j)                                      \
            xb[j] = __shfl_sync(0xFFFFFFFFu, wpack, j);                    \
        _Pragma("unroll")                                                  \
        for (int j = 0; j < 32; j += 2) {                                  \
            aA0 = __hfma2(EtA[j],     as_bf2(xb[j]),     aA0);             \
            aB0 = __hfma2(EtB[j],     as_bf2(xb[j]),     aB0);             \
            aA1 = __hfma2(EtA[j + 1], as_bf2(xb[j + 1]), aA1);             \
            aB1 = __hfma2(EtB[j + 1], as_bf2(xb[j + 1]), aB1);             \
        }                                                                  \
        float2 fA = __bfloat1622float2(__hadd2(aA0, aA1));                 \
        float2 fB = __bfloat1622float2(__hadd2(aB0, aB1));                 \
        float w0 = (fA.x + fA.y) * (CE).x;                                 \
        float w1 = (fB.x + fB.y) * (CE).y;                                 \
        if (RESC) {                                                        \
            __nv_bfloat162 mh = z;                                         \
            _Pragma("unroll")                                              \
            for (int j = 0; j < 32; ++j)                                   \
                mh = __hmax2(mh, as_bf2(xb[j]));                           \
            float2 m2 = __bfloat1622float2(mh);                            \
            float mx = fmaxf(m2.x, m2.y);                                  \
            /* mx identical on all lanes (built from broadcast values) */  \
            if (mx > 0.0f) {                                               \
                int k = ((__float_as_int(mx) >> 23) & 0xFF) - 127;         \
                ktot += k;                                                 \
                float sc = __int_as_float((127 - k) << 23);                \
                w0 *= sc; w1 *= sc;                                        \
            }                                                              \
        }                                                                  \
        wpack = as_u32(__floats2bfloat162_rn(w0, w1));                     \
    }

        for (int t0 = 0; t0 < len4; t0 += 4) {
            // load next group's raw emissions (clamped; garbage never used)
            const int p = min(t0 + 4, T_ - 4);
            float2 g0 = fb2[(p + 0) * 32 + lane];
            float2 g1 = fb2[(p + 1) * 32 + lane];
            float2 g2 = fb2[(p + 2) * 32 + lane];
            float2 g3 = fb2[(p + 3) * 32 + lane];

            STEP(ce0, false);
            STEP(ce1, false);
            STEP(ce2, false);
            STEP(ce3, true);

            ce0 = make_float2(__expf(g0.x), __expf(g0.y));
            ce1 = make_float2(__expf(g1.x), __expf(g1.y));
            ce2 = make_float2(__expf(g2.x), __expf(g2.y));
            ce3 = make_float2(__expf(g3.x), __expf(g3.y));
        }

        // remainder (0-3 steps; <=3 unscaled steps cannot overflow bf16)
        const int rem = len - len4;
        if (rem > 0) STEP(ce0, false);
        if (rem > 1) STEP(ce1, false);
        if (rem > 2) STEP(ce2, false);
#undef STEP

        // ---- terminal: fwd = ktot*ln2 + log(sum_i v[i]*exp(trans[STOP,i])) --
        float2 vf = __bfloat1622float2(as_bf2(wpack));
        float u = vf.x * EtS0 + vf.y * EtS1;
#pragma unroll
        for (int off = 16; off; off >>= 1) {
            u    += __shfl_xor_sync(0xFFFFFFFFu, u,    off);
            gold += __shfl_xor_sync(0xFFFFFFFFu, gold, off);
        }
        if (lane == 0) {
            float fwd = (float)((double)ktot * 0.69314718055994530942)
                      + logf(u);
            atomicAdd(out, (fwd - gold) * (1.0f / (float)B_));
        }
    }
}

extern "C" void kernel_launch(void* const* d_in, const int* in_sizes, int n_in,
                              void* d_out, int out_size)
{
    const float* feats   = (const float*)d_in[0];
    const int*   lengths = (const int*)  d_in[1];
    const int*   tags    = (const int*)  d_in[2];
    const float* trans   = (const float*)d_in[3];
    float* out = (float*)d_out;

    order_kernel<<<4, 256>>>(lengths, out);
    crf_bf16<<<148, 128>>>(feats, lengths, tags, trans, out);
}